// round 8
// baseline (speedup 1.0000x reference)
#include <cuda_runtime.h>

// CRF NLL, exp-domain forward scan. 128 blocks x 128 threads:
// 4 independent chains per block, ONE chain per WARP (one warp per SMSP),
// no CTA barriers. Lane owns tags {2*lane, 2*lane+1}; q exchanged via
// warp-private smem + __syncwarp. Rescaling by exact powers of 2
// (exponent-field extraction), so no MUFU in the scan loop except the
// prefetch __expf of feats.

constexpr int Bb = 512;
constexpr int Ss = 512;
constexpr int Tt = 64;
constexpr int START = Tt - 2;
constexpr int STOP  = Tt - 1;
constexpr int PD    = 4;      // feats prefetch depth (steps)
constexpr int WPB   = 4;      // warps (chains) per block
constexpr int NBLK  = Bb / WPB;   // 128

__device__ float g_partial[Bb];
__device__ unsigned int g_count = 0;

typedef unsigned long long u64;

static __device__ __forceinline__ u64 fma2(u64 a, u64 b, u64 c) {
    u64 d;
    asm("fma.rn.f32x2 %0, %1, %2, %3;" : "=l"(d) : "l"(a), "l"(b), "l"(c));
    return d;
}
static __device__ __forceinline__ u64 add2(u64 a, u64 b) {
    u64 d;
    asm("add.rn.f32x2 %0, %1, %2;" : "=l"(d) : "l"(a), "l"(b));
    return d;
}
static __device__ __forceinline__ u64 pack2(float lo, float hi) {
    u64 d;
    asm("mov.b64 %0, {%1, %2};" : "=l"(d) : "f"(lo), "f"(hi));
    return d;
}
static __device__ __forceinline__ void unpack2(u64 v, float& lo, float& hi) {
    asm("mov.b64 {%0, %1}, %2;" : "=f"(lo), "=f"(hi) : "l"(v));
}
static __device__ __forceinline__ float warp_sum(float v) {
    #pragma unroll
    for (int off = 16; off > 0; off >>= 1)
        v += __shfl_xor_sync(0xffffffffu, v, off);
    return v;
}
static __device__ __forceinline__ int warp_sum_i(int v) {
    #pragma unroll
    for (int off = 16; off > 0; off >>= 1)
        v += __shfl_xor_sync(0xffffffffu, v, off);
    return v;
}

__global__ __launch_bounds__(32 * WPB) void crf_kernel(
    const float* __restrict__ feats,
    const unsigned char* __restrict__ mask8,
    const int* __restrict__ tags,
    const float* __restrict__ trans,
    float* __restrict__ out)
{
    const int w    = threadIdx.x >> 5;     // warp in block (0..3) -> SMSP w
    const int lane = threadIdx.x & 31;
    const int b    = blockIdx.x * WPB + w; // this warp's batch
    const int to0  = 2 * lane;             // owned tags: to0, to0+1

    __shared__ __align__(16) float qbuf[WPB][2][Tt];  // per-warp q, double-buffered

    // ---- mask layout probe (uint8 vs int32) + sequence length ----
    const int* mask32 = reinterpret_cast<const int*>(mask8);
    const bool is32 = (mask8[0] == 1 && mask8[1] == 0 && mask8[2] == 0 && mask8[3] == 0);

    int cnt = 0;
    #pragma unroll
    for (int k = 0; k < Ss / 32; ++k) {
        int s  = lane + k * 32;
        int mv = is32 ? mask32[b * Ss + s] : (int)mask8[b * Ss + s];
        cnt += (mv != 0);
    }
    const int L = warp_sum_i(cnt);          // >= S/2 = 256

    const float* fb = feats + (size_t)b * Ss * Tt;
    const int*   tg = tags + b * Ss;

    // ---- gold path score ----
    float gsum = 0.f;
    for (int s = lane; s < L; s += 32) {
        int t1 = tg[s];
        int t0 = (s == 0) ? START : tg[s - 1];
        gsum += fb[s * Tt + t1] + trans[t0 * Tt + t1];
    }
    const float gold = warp_sum(gsum) + trans[tg[L - 1] * Tt + STOP];

    // ---- E pairs along FROM for both owned tags ----
    u64 E2a[Tt / 2], E2b[Tt / 2];
    #pragma unroll
    for (int k = 0; k < Tt / 2; ++k) {
        E2a[k] = pack2(__expf(trans[(2 * k) * Tt + to0]),
                       __expf(trans[(2 * k + 1) * Tt + to0]));
        E2b[k] = pack2(__expf(trans[(2 * k) * Tt + to0 + 1]),
                       __expf(trans[(2 * k + 1) * Tt + to0 + 1]));
    }

    // ---- init: part_0 = f_0 + trans[START,:]; q_0 = exp(part_0 - part_0[0]) ----
    const float c0 = fb[0] + trans[START * Tt];   // broadcast loads
    {
        float2 f0 = *reinterpret_cast<const float2*>(fb + to0);
        float2 q0;
        q0.x = __expf(f0.x + trans[START * Tt + to0]     - c0);
        q0.y = __expf(f0.y + trans[START * Tt + to0 + 1] - c0);
        *reinterpret_cast<float2*>(&qbuf[w][0][to0]) = q0;
    }
    int eSum = 0;   // sum of power-of-2 rescale exponents (uniform across warp)

    // ---- feats pipeline: exp(f) at prefetch time (off critical path) ----
    float efa[PD], efb[PD];
    #pragma unroll
    for (int r = 0; r < PD; ++r) {
        float2 f = *reinterpret_cast<const float2*>(fb + (1 + r) * Tt + to0);
        efa[r] = __expf(f.x);
        efb[r] = __expf(f.y);
    }

    float cur0 = 0.f, cur1 = 0.f;

    auto step = [&](int s, float ea, float eb) {
        __syncwarp();
        const ulonglong2* qp = reinterpret_cast<const ulonglong2*>(qbuf[w][(s - 1) & 1]);

        ulonglong2 v = qp[0];
        float q0, qd;
        unpack2(v.x, q0, qd);
        // exact power-of-2 rescale: scale = 2^(127 - e(q0))
        const unsigned ebits = __float_as_uint(q0) >> 23;
        eSum += (int)ebits - 127;
        const float scale = __uint_as_float((254u - ebits) << 23);

        u64 a0 = fma2(v.x, E2a[0], 0ull);
        u64 a1 = fma2(v.y, E2a[1], 0ull);
        u64 b0 = fma2(v.x, E2b[0], 0ull);
        u64 b1 = fma2(v.y, E2b[1], 0ull);
        #pragma unroll
        for (int j = 1; j < 16; ++j) {
            v = qp[j];
            a0 = fma2(v.x, E2a[2 * j],     a0);
            a1 = fma2(v.y, E2a[2 * j + 1], a1);
            b0 = fma2(v.x, E2b[2 * j],     b0);
            b1 = fma2(v.y, E2b[2 * j + 1], b1);
        }
        float alo, ahi, blo, bhi;
        unpack2(add2(a0, a1), alo, ahi);
        unpack2(add2(b0, b1), blo, bhi);
        cur0 = (alo + ahi) * (ea * scale);
        cur1 = (blo + bhi) * (eb * scale);
        *reinterpret_cast<float2*>(&qbuf[w][s & 1][to0]) = make_float2(cur0, cur1);
    };

    // ---- forward scan, unrolled x PD with prefetch ----
    int s = 1;
    for (; s + (PD - 1) < L; ) {
        #pragma unroll
        for (int r = 0; r < PD; ++r) {
            const float ea = efa[r], eb = efb[r];
            if (s + PD < L) {
                float2 f = *reinterpret_cast<const float2*>(fb + (s + PD) * Tt + to0);
                efa[r] = __expf(f.x);
                efb[r] = __expf(f.y);
            }
            step(s, ea, eb);
            ++s;
        }
    }
    for (; s < L; ++s) {
        int r = (s - 1) & (PD - 1);
        step(s, efa[r], efb[r]);
    }

    // ---- final transition to STOP ----
    float fin = cur0 * __expf(trans[to0 * Tt + STOP])
              + cur1 * __expf(trans[(to0 + 1) * Tt + STOP]);
    fin = warp_sum(fin);
    const float nll = (c0 + (float)eSum * 0.69314718055994531f + __logf(fin)) - gold;

    unsigned int c = 0;
    if (lane == 0) {
        g_partial[b] = nll;
        __threadfence();
        c = atomicAdd(&g_count, 1u);
    }
    c = __shfl_sync(0xffffffffu, c, 0);

    // ---- last warp: deterministic fixed-order reduction over batches ----
    if (c == (unsigned)(Bb - 1)) {
        __threadfence();
        float sum = 0.f;
        #pragma unroll
        for (int k = 0; k < Bb / 32; ++k) {
            float v;
            asm volatile("ld.global.cg.f32 %0, [%1];" : "=f"(v)
                         : "l"(&g_partial[lane + k * 32]));
            sum += v;
        }
        sum = warp_sum(sum);
        if (lane == 0) {
            out[0] = sum;
            g_count = 0;   // reset for next (graph-replayed) launch
        }
    }
}

extern "C" void kernel_launch(void* const* d_in, const int* in_sizes, int n_in,
                              void* d_out, int out_size)
{
    (void)in_sizes; (void)n_in; (void)out_size;
    const float*         feats = (const float*)d_in[0];
    const unsigned char* mask  = (const unsigned char*)d_in[1];
    const int*           tags  = (const int*)d_in[2];
    const float*         trans = (const float*)d_in[3];

    crf_kernel<<<NBLK, 32 * WPB>>>(feats, mask, tags, trans, (float*)d_out);
}

// round 9
// speedup vs baseline: 1.1966x; 1.1966x over previous
#include <cuda_runtime.h>

// CRF NLL via BIDIRECTIONAL exp-domain scan: the recurrence is linear
// (answer = Estop^T D_{L-1} E^T ... D_1 E^T P_0), so block b runs the
// forward half (P_h) and block b+512 runs the backward co-vector half
// (u_h); answer = log(dot(P_h, u_h)). Sequential depth halves: 512 -> 256.
// Per-step body = R3's proven 32xFMA2 smem-exchange kernel with exact
// power-of-2 rescaling (no MUFU rescale in the loop).

constexpr int Bb = 512;
constexpr int Ss = 512;
constexpr int Tt = 64;
constexpr int START = Tt - 2;
constexpr int STOP  = Tt - 1;
constexpr int PD    = 8;     // feats prefetch depth (steps)
constexpr float LN2 = 0.69314718055994531f;

__device__ float g_meet[Bb][2][68];   // [.][0]: P_h vec,64=eF,65=c0,66=gold ; [.][1]: u_h vec,64=eB
__device__ float g_partial[Bb];
__device__ unsigned g_pair[Bb];       // zero-initialized
__device__ unsigned g_count = 0;

typedef unsigned long long u64;

static __device__ __forceinline__ u64 fma2(u64 a, u64 b, u64 c) {
    u64 d;
    asm("fma.rn.f32x2 %0, %1, %2, %3;" : "=l"(d) : "l"(a), "l"(b), "l"(c));
    return d;
}
static __device__ __forceinline__ u64 add2(u64 a, u64 b) {
    u64 d;
    asm("add.rn.f32x2 %0, %1, %2;" : "=l"(d) : "l"(a), "l"(b));
    return d;
}
static __device__ __forceinline__ u64 pack2(float lo, float hi) {
    u64 d;
    asm("mov.b64 %0, {%1, %2};" : "=l"(d) : "f"(lo), "f"(hi));
    return d;
}
static __device__ __forceinline__ void unpack2(u64 v, float& lo, float& hi) {
    asm("mov.b64 {%0, %1}, %2;" : "=f"(lo), "=f"(hi) : "l"(v));
}
static __device__ __forceinline__ float ldcg(const float* p) {
    float v;
    asm volatile("ld.global.cg.f32 %0, [%1];" : "=f"(v) : "l"(p));
    return v;
}

__global__ __launch_bounds__(Tt) void crf_kernel(
    const float* __restrict__ feats,
    const unsigned char* __restrict__ mask8,
    const int* __restrict__ tags,
    const float* __restrict__ trans,
    float* __restrict__ out)
{
    const bool isF = (blockIdx.x < Bb);
    const int  b   = isF ? blockIdx.x : blockIdx.x - Bb;
    const int  to  = threadIdx.x;   // 0..63

    __shared__ ulonglong2 qbuf[2][16];   // 64 floats per buffer
    __shared__ float red[Tt];
    __shared__ int   ired[Tt];
    __shared__ int   shL;
    __shared__ unsigned sOld, sCnt;

    // ---- mask layout probe (uint8 vs int32) + sequence length ----
    const int* mask32 = reinterpret_cast<const int*>(mask8);
    const bool is32 = (mask8[0] == 1 && mask8[1] == 0 && mask8[2] == 0 && mask8[3] == 0);

    int cnt = 0;
    #pragma unroll
    for (int k = 0; k < Ss / Tt; ++k) {
        int s  = to + k * Tt;
        int mv = is32 ? mask32[b * Ss + s] : (int)mask8[b * Ss + s];
        cnt += (mv != 0);
    }
    ired[to] = cnt;
    __syncthreads();
    if (to == 0) {
        int L = 0;
        #pragma unroll
        for (int i = 0; i < Tt; ++i) L += ired[i];
        shL = L;
    }
    __syncthreads();
    const int L = shL;     // >= 256
    const int h = L / 2;   // forward: steps 1..h ; backward: steps L-1..h+1

    const float* fb = feats + (size_t)b * Ss * Tt;
    const int*   tg = tags + b * Ss;

    float gold = 0.f, c0f = 0.f;
    int   eSum = 0;
    float cur  = 0.f;

    // ---- E pairs: forward needs column 'to' of E; backward needs row 'to' ----
    u64 E2[Tt / 2];
    if (isF) {
        #pragma unroll
        for (int k = 0; k < Tt / 2; ++k)
            E2[k] = pack2(__expf(trans[(2 * k) * Tt + to]),
                          __expf(trans[(2 * k + 1) * Tt + to]));
    } else {
        #pragma unroll
        for (int k = 0; k < Tt / 2; ++k)
            E2[k] = pack2(__expf(trans[to * Tt + 2 * k]),
                          __expf(trans[to * Tt + 2 * k + 1]));
    }

    if (isF) {
        // ---- gold path score (full sequence, off critical path) ----
        float gsum = 0.f;
        for (int s = to; s < L; s += Tt) {
            int t1 = tg[s];
            int t0 = (s == 0) ? START : tg[s - 1];
            gsum += fb[s * Tt + t1] + trans[t0 * Tt + t1];
        }
        red[to] = gsum;
        __syncthreads();
        if (to == 0) {
            #pragma unroll
            for (int i = 0; i < Tt; ++i) gold += red[i];
            gold += trans[tg[L - 1] * Tt + STOP];
        }
        __syncthreads();

        // ---- init: P_0 = exp(f_0 + T[START,:]); store normalized by c0 ----
        const float c0 = fb[0] + trans[START * Tt];
        c0f = c0;
        reinterpret_cast<float*>(qbuf[0])[to] =
            __expf(fb[to] + trans[START * Tt + to] - c0);
        __syncthreads();

        float fp[PD];
        #pragma unroll
        for (int r = 0; r < PD; ++r) fp[r] = fb[(1 + r) * Tt + to];

        auto step = [&](int s, float f) {
            const ulonglong2* qp = qbuf[(s - 1) & 1];
            ulonglong2 w = qp[0];
            float q0, q1d;
            unpack2(w.x, q0, q1d);
            const unsigned eb = __float_as_uint(q0) >> 23;
            eSum += (int)eb - 127;
            const float sc = __expf(f) * __uint_as_float((254u - eb) << 23);

            u64 a0 = fma2(w.x, E2[0], 0ull);
            u64 a1 = fma2(w.y, E2[1], 0ull);
            u64 a2 = 0ull, a3 = 0ull;
            #pragma unroll
            for (int j = 1; j < 16; ++j) {
                w = qp[j];
                if (j & 1) { a2 = fma2(w.x, E2[2 * j], a2); a3 = fma2(w.y, E2[2 * j + 1], a3); }
                else       { a0 = fma2(w.x, E2[2 * j], a0); a1 = fma2(w.y, E2[2 * j + 1], a1); }
            }
            float lo, hi;
            unpack2(add2(add2(a0, a2), add2(a1, a3)), lo, hi);
            const float raw = (lo + hi) * sc;
            reinterpret_cast<float*>(qbuf[s & 1])[to] = raw;
            cur = raw;
            __syncthreads();
        };

        int s = 1;
        const int end = h + 1;
        for (; s + (PD - 1) < end; ) {
            #pragma unroll
            for (int r = 0; r < PD; ++r) {
                const float f = fp[r];
                if (s + PD < end) fp[r] = fb[(s + PD) * Tt + to];
                step(s, f);
                ++s;
            }
        }
        for (; s < end; ++s) step(s, fp[(s - 1) & (PD - 1)]);

        // ---- publish P_h ----
        g_meet[b][0][to] = cur;
        if (to == 0) {
            g_meet[b][0][64] = (float)eSum;
            g_meet[b][0][65] = c0f;
            g_meet[b][0][66] = gold;
        }
    } else {
        // ---- backward co-vector: u_{L-1} = Estop; u_{t-1} = E (ef_t . u_t) ----
        const float u0 = __expf(trans[to * Tt + STOP]);
        cur = u0;
        reinterpret_cast<float*>(qbuf[0])[to] = u0 * __expf(fb[(L - 1) * Tt + to]);
        __syncthreads();

        const int nB = L - 1 - h;   // >= 127
        float fp[PD];
        #pragma unroll
        for (int r = 0; r < PD; ++r) fp[r] = fb[(size_t)(L - 2 - r) * Tt + to];

        auto bstep = [&](int j, float f) {
            const ulonglong2* qp = qbuf[j & 1];
            ulonglong2 w = qp[0];
            float w0, w1d;
            unpack2(w.x, w0, w1d);
            const unsigned eb = __float_as_uint(w0) >> 23;
            eSum += (int)eb - 127;
            const float sc = __uint_as_float((254u - eb) << 23);

            u64 a0 = fma2(w.x, E2[0], 0ull);
            u64 a1 = fma2(w.y, E2[1], 0ull);
            u64 a2 = 0ull, a3 = 0ull;
            #pragma unroll
            for (int j2 = 1; j2 < 16; ++j2) {
                w = qp[j2];
                if (j2 & 1) { a2 = fma2(w.x, E2[2 * j2], a2); a3 = fma2(w.y, E2[2 * j2 + 1], a3); }
                else        { a0 = fma2(w.x, E2[2 * j2], a0); a1 = fma2(w.y, E2[2 * j2 + 1], a1); }
            }
            float lo, hi;
            unpack2(add2(add2(a0, a2), add2(a1, a3)), lo, hi);
            const float u = (lo + hi) * sc;          // u_{t-1}[to]
            cur = u;
            reinterpret_cast<float*>(qbuf[(j + 1) & 1])[to] = u * __expf(f);
            __syncthreads();
        };

        int j = 0;
        for (; j + (PD - 1) < nB; ) {
            #pragma unroll
            for (int r = 0; r < PD; ++r) {
                const float f = fp[r];
                if (j + PD < nB) fp[r] = fb[(size_t)(L - 2 - j - PD) * Tt + to];
                bstep(j, f);
                ++j;
            }
        }
        for (; j < nB; ++j) bstep(j, fp[j & (PD - 1)]);

        // ---- publish u_h ----
        g_meet[b][1][to] = cur;
        if (to == 0) g_meet[b][1][64] = (float)eSum;
    }

    // ---- pair rendezvous: second arriver combines ----
    __threadfence();
    __syncthreads();
    if (to == 0) sOld = atomicAdd(&g_pair[b], 1u);
    __syncthreads();
    if (sOld != 1u) return;   // first arriver exits

    // combine: dot(P_h, u_h), fixed order
    const float other = ldcg(&g_meet[b][isF ? 1 : 0][to]);
    red[to] = cur * other;
    __syncthreads();
    if (to == 0) {
        float dot = 0.f;
        #pragma unroll
        for (int i = 0; i < Tt; ++i) dot += red[i];
        float eF, eB, c0v, gv;
        if (isF) {
            eF = (float)eSum; c0v = c0f; gv = gold;
            eB = ldcg(&g_meet[b][1][64]);
        } else {
            eB = (float)eSum;
            eF  = ldcg(&g_meet[b][0][64]);
            c0v = ldcg(&g_meet[b][0][65]);
            gv  = ldcg(&g_meet[b][0][66]);
        }
        g_partial[b] = c0v + (eF + eB) * LN2 + __logf(dot) - gv;
        g_pair[b] = 0;                      // reset for graph replay
        __threadfence();
        sCnt = atomicAdd(&g_count, 1u);
    }
    __syncthreads();

    // ---- last combiner: deterministic fixed-order reduction over batches ----
    if (sCnt == (unsigned)(Bb - 1)) {
        __threadfence();
        float sum = 0.f;
        #pragma unroll
        for (int k = 0; k < Bb / Tt; ++k)
            sum += ldcg(&g_partial[to + k * Tt]);
        red[to] = sum;
        __syncthreads();
        if (to == 0) {
            float tot = 0.f;
            #pragma unroll
            for (int i = 0; i < Tt; ++i) tot += red[i];
            out[0] = tot;
            g_count = 0;                    // reset for graph replay
        }
    }
}

extern "C" void kernel_launch(void* const* d_in, const int* in_sizes, int n_in,
                              void* d_out, int out_size)
{
    (void)in_sizes; (void)n_in; (void)out_size;
    const float*         feats = (const float*)d_in[0];
    const unsigned char* mask  = (const unsigned char*)d_in[1];
    const int*           tags  = (const int*)d_in[2];
    const float*         trans = (const float*)d_in[3];

    crf_kernel<<<2 * Bb, Tt>>>(feats, mask, tags, trans, (float*)d_out);
}

// round 10
// speedup vs baseline: 1.4143x; 1.1820x over previous
#include <cuda_runtime.h>

// CRF NLL, bidirectional exp-domain scan with SINGLE-WARP chains.
// 1024 blocks x 32 threads: block b (<512) runs the forward half of batch b
// (P_h, steps 1..h); block b+512 runs the backward co-vector half
// (u_h, steps L-1..h+1). answer = log(dot(P_h, u_h)).
// No CTA barriers: q exchanged via warp-private smem + __syncwarp.
// Exact power-of-2 rescaling (exponent extraction) -> no MUFU in the loop
// except prefetch __expf of feats. Lane owns tags {2*lane, 2*lane+1}.

constexpr int Bb = 512;
constexpr int Ss = 512;
constexpr int Tt = 64;
constexpr int START = Tt - 2;
constexpr int STOP  = Tt - 1;
constexpr int PD    = 4;     // feats prefetch depth (steps)
constexpr float LN2 = 0.69314718055994531f;

__device__ float g_meet[Bb][2][68];  // [.][0]: P_h,64=eF,65=c0,66=gold ; [.][1]: u_h,64=eB
__device__ float g_partial[Bb];
__device__ unsigned g_pair[Bb];      // zero-initialized
__device__ unsigned g_count = 0;

typedef unsigned long long u64;

static __device__ __forceinline__ u64 fma2(u64 a, u64 b, u64 c) {
    u64 d;
    asm("fma.rn.f32x2 %0, %1, %2, %3;" : "=l"(d) : "l"(a), "l"(b), "l"(c));
    return d;
}
static __device__ __forceinline__ u64 add2(u64 a, u64 b) {
    u64 d;
    asm("add.rn.f32x2 %0, %1, %2;" : "=l"(d) : "l"(a), "l"(b));
    return d;
}
static __device__ __forceinline__ u64 pack2(float lo, float hi) {
    u64 d;
    asm("mov.b64 %0, {%1, %2};" : "=l"(d) : "f"(lo), "f"(hi));
    return d;
}
static __device__ __forceinline__ void unpack2(u64 v, float& lo, float& hi) {
    asm("mov.b64 {%0, %1}, %2;" : "=f"(lo), "=f"(hi) : "l"(v));
}
static __device__ __forceinline__ float ldcg(const float* p) {
    float v;
    asm volatile("ld.global.cg.f32 %0, [%1];" : "=f"(v) : "l"(p));
    return v;
}
static __device__ __forceinline__ float warp_sum(float v) {
    #pragma unroll
    for (int off = 16; off > 0; off >>= 1)
        v += __shfl_xor_sync(0xffffffffu, v, off);
    return v;
}
static __device__ __forceinline__ int warp_sum_i(int v) {
    #pragma unroll
    for (int off = 16; off > 0; off >>= 1)
        v += __shfl_xor_sync(0xffffffffu, v, off);
    return v;
}

__global__ __launch_bounds__(32) void crf_kernel(
    const float* __restrict__ feats,
    const unsigned char* __restrict__ mask8,
    const int* __restrict__ tags,
    const float* __restrict__ trans,
    float* __restrict__ out)
{
    const bool isF = (blockIdx.x < Bb);
    const int  b   = isF ? blockIdx.x : blockIdx.x - Bb;
    const int  lane = threadIdx.x;      // 0..31
    const int  to0  = 2 * lane;         // owned tags

    __shared__ __align__(16) float qbuf[2][Tt];   // q / w vector, double-buffered

    // ---- mask layout probe (uint8 vs int32) + sequence length ----
    const int* mask32 = reinterpret_cast<const int*>(mask8);
    const bool is32 = (mask8[0] == 1 && mask8[1] == 0 && mask8[2] == 0 && mask8[3] == 0);

    int cnt = 0;
    #pragma unroll
    for (int k = 0; k < Ss / 32; ++k) {
        int s  = lane + k * 32;
        int mv = is32 ? mask32[b * Ss + s] : (int)mask8[b * Ss + s];
        cnt += (mv != 0);
    }
    const int L = warp_sum_i(cnt);   // >= 256
    const int h = L / 2;             // forward: steps 1..h ; backward: L-1..h+1

    const float* fb = feats + (size_t)b * Ss * Tt;
    const int*   tg = tags + b * Ss;

    float gold = 0.f, c0f = 0.f;
    int   eSum = 0;
    float cur0 = 0.f, cur1 = 0.f;

    // ---- E pairs: forward needs columns {to0,to0+1}; backward needs rows ----
    u64 E2a[Tt / 2], E2b[Tt / 2];
    if (isF) {
        #pragma unroll
        for (int k = 0; k < Tt / 2; ++k) {
            E2a[k] = pack2(__expf(trans[(2 * k) * Tt + to0]),
                           __expf(trans[(2 * k + 1) * Tt + to0]));
            E2b[k] = pack2(__expf(trans[(2 * k) * Tt + to0 + 1]),
                           __expf(trans[(2 * k + 1) * Tt + to0 + 1]));
        }
    } else {
        #pragma unroll
        for (int k = 0; k < Tt / 2; ++k) {
            E2a[k] = pack2(__expf(trans[to0 * Tt + 2 * k]),
                           __expf(trans[to0 * Tt + 2 * k + 1]));
            E2b[k] = pack2(__expf(trans[(to0 + 1) * Tt + 2 * k]),
                           __expf(trans[(to0 + 1) * Tt + 2 * k + 1]));
        }
    }

    // shared FMA core: 64 MACs per owned tag from the 64-wide smem vector
    auto matvec = [&](const ulonglong2* qp, float& o0, float& o1, float& w0out) {
        ulonglong2 v = qp[0];
        float w0, wd;
        unpack2(v.x, w0, wd);
        w0out = w0;
        u64 a0 = fma2(v.x, E2a[0], 0ull);
        u64 a1 = fma2(v.y, E2a[1], 0ull);
        u64 b0 = fma2(v.x, E2b[0], 0ull);
        u64 b1 = fma2(v.y, E2b[1], 0ull);
        #pragma unroll
        for (int j = 1; j < 16; ++j) {
            v = qp[j];
            a0 = fma2(v.x, E2a[2 * j],     a0);
            a1 = fma2(v.y, E2a[2 * j + 1], a1);
            b0 = fma2(v.x, E2b[2 * j],     b0);
            b1 = fma2(v.y, E2b[2 * j + 1], b1);
        }
        float alo, ahi, blo, bhi;
        unpack2(add2(a0, a1), alo, ahi);
        unpack2(add2(b0, b1), blo, bhi);
        o0 = alo + ahi;
        o1 = blo + bhi;
    };

    if (isF) {
        // ---- gold path score (full sequence) ----
        float gsum = 0.f;
        for (int s = lane; s < L; s += 32) {
            int t1 = tg[s];
            int t0 = (s == 0) ? START : tg[s - 1];
            gsum += fb[s * Tt + t1] + trans[t0 * Tt + t1];
        }
        gold = warp_sum(gsum) + trans[tg[L - 1] * Tt + STOP];

        // ---- init: P_0 = exp(f_0 + T[START,:]), normalized by c0 ----
        const float c0 = fb[0] + trans[START * Tt];
        c0f = c0;
        {
            float2 f0 = *reinterpret_cast<const float2*>(fb + to0);
            float2 q0;
            q0.x = __expf(f0.x + trans[START * Tt + to0]     - c0);
            q0.y = __expf(f0.y + trans[START * Tt + to0 + 1] - c0);
            *reinterpret_cast<float2*>(&qbuf[0][to0]) = q0;
        }

        float efa[PD], efb[PD];
        #pragma unroll
        for (int r = 0; r < PD; ++r) {
            float2 f = *reinterpret_cast<const float2*>(fb + (1 + r) * Tt + to0);
            efa[r] = __expf(f.x);
            efb[r] = __expf(f.y);
        }

        auto step = [&](int s, float ea, float eb) {
            __syncwarp();
            const ulonglong2* qp = reinterpret_cast<const ulonglong2*>(qbuf[(s - 1) & 1]);
            float o0, o1, q0;
            matvec(qp, o0, o1, q0);
            const unsigned ebits = __float_as_uint(q0) >> 23;
            eSum += (int)ebits - 127;
            const float scale = __uint_as_float((254u - ebits) << 23);
            cur0 = o0 * (ea * scale);
            cur1 = o1 * (eb * scale);
            *reinterpret_cast<float2*>(&qbuf[s & 1][to0]) = make_float2(cur0, cur1);
        };

        const int end = h + 1;   // steps 1..h
        int s = 1;
        for (; s + (PD - 1) < end; ) {
            #pragma unroll
            for (int r = 0; r < PD; ++r) {
                const float ea = efa[r], eb = efb[r];
                // safe: s+PD <= h+PD < Ss
                float2 f = *reinterpret_cast<const float2*>(fb + (s + PD) * Tt + to0);
                efa[r] = __expf(f.x);
                efb[r] = __expf(f.y);
                step(s, ea, eb);
                ++s;
            }
        }
        for (; s < end; ++s) {
            int r = (s - 1) & (PD - 1);
            step(s, efa[r], efb[r]);
        }

        // ---- publish P_h ----
        g_meet[b][0][to0]     = cur0;
        g_meet[b][0][to0 + 1] = cur1;
        if (lane == 0) {
            g_meet[b][0][64] = (float)eSum;
            g_meet[b][0][65] = c0f;
            g_meet[b][0][66] = gold;
        }
    } else {
        // ---- backward: u_{L-1} = Estop; w_t = u_t . ef_t; u_{t-1} = E w_t ----
        {
            float2 f0 = *reinterpret_cast<const float2*>(fb + (size_t)(L - 1) * Tt + to0);
            cur0 = __expf(trans[to0 * Tt + STOP]);
            cur1 = __expf(trans[(to0 + 1) * Tt + STOP]);
            *reinterpret_cast<float2*>(&qbuf[0][to0]) =
                make_float2(cur0 * __expf(f0.x), cur1 * __expf(f0.y));
        }

        const int nB = L - 1 - h;   // >= 127
        float efa[PD], efb[PD];
        #pragma unroll
        for (int r = 0; r < PD; ++r) {
            float2 f = *reinterpret_cast<const float2*>(fb + (size_t)(L - 2 - r) * Tt + to0);
            efa[r] = __expf(f.x);
            efb[r] = __expf(f.y);
        }

        auto bstep = [&](int j, float ea, float eb) {
            __syncwarp();
            const ulonglong2* qp = reinterpret_cast<const ulonglong2*>(qbuf[j & 1]);
            float o0, o1, w0;
            matvec(qp, o0, o1, w0);
            const unsigned ebits = __float_as_uint(w0) >> 23;
            eSum += (int)ebits - 127;
            const float scale = __uint_as_float((254u - ebits) << 23);
            cur0 = o0 * scale;          // u_{t-1}[to0]
            cur1 = o1 * scale;
            *reinterpret_cast<float2*>(&qbuf[(j + 1) & 1][to0]) =
                make_float2(cur0 * ea, cur1 * eb);
        };

        int j = 0;
        for (; j + (PD - 1) < nB; ) {
            #pragma unroll
            for (int r = 0; r < PD; ++r) {
                const float ea = efa[r], eb = efb[r];
                // safe: L-2-j-PD >= h-3 >= 0
                float2 f = *reinterpret_cast<const float2*>(
                    fb + (size_t)(L - 2 - j - PD) * Tt + to0);
                efa[r] = __expf(f.x);
                efb[r] = __expf(f.y);
                bstep(j, ea, eb);
                ++j;
            }
        }
        for (; j < nB; ++j) {
            int r = j & (PD - 1);
            bstep(j, efa[r], efb[r]);
        }

        // ---- publish u_h ----
        g_meet[b][1][to0]     = cur0;
        g_meet[b][1][to0 + 1] = cur1;
        if (lane == 0) g_meet[b][1][64] = (float)eSum;
    }

    // ---- pair rendezvous: second arriver combines ----
    __threadfence();
    unsigned old = 0;
    if (lane == 0) old = atomicAdd(&g_pair[b], 1u);
    old = __shfl_sync(0xffffffffu, old, 0);
    if (old != 1u) return;   // first arriver exits

    __threadfence();
    const float* o = &g_meet[b][isF ? 1 : 0][0];
    float dot = warp_sum(cur0 * ldcg(o + to0) + cur1 * ldcg(o + to0 + 1));

    unsigned c = 0;
    if (lane == 0) {
        float eF, eB, c0v, gv;
        if (isF) {
            eF = (float)eSum; c0v = c0f; gv = gold;
            eB = ldcg(&g_meet[b][1][64]);
        } else {
            eB = (float)eSum;
            eF  = ldcg(&g_meet[b][0][64]);
            c0v = ldcg(&g_meet[b][0][65]);
            gv  = ldcg(&g_meet[b][0][66]);
        }
        g_partial[b] = c0v + (eF + eB) * LN2 + __logf(dot) - gv;
        g_pair[b] = 0;                       // reset for graph replay
        __threadfence();
        c = atomicAdd(&g_count, 1u);
    }
    c = __shfl_sync(0xffffffffu, c, 0);

    // ---- last combiner: deterministic fixed-order reduction over batches ----
    if (c == (unsigned)(Bb - 1)) {
        __threadfence();
        float sum = 0.f;
        #pragma unroll
        for (int k = 0; k < Bb / 32; ++k)
            sum += ldcg(&g_partial[lane + k * 32]);
        sum = warp_sum(sum);
        if (lane == 0) {
            out[0] = sum;
            g_count = 0;                     // reset for graph replay
        }
    }
}

extern "C" void kernel_launch(void* const* d_in, const int* in_sizes, int n_in,
                              void* d_out, int out_size)
{
    (void)in_sizes; (void)n_in; (void)out_size;
    const float*         feats = (const float*)d_in[0];
    const unsigned char* mask  = (const unsigned char*)d_in[1];
    const int*           tags  = (const int*)d_in[2];
    const float*         trans = (const float*)d_in[3];

    crf_kernel<<<2 * Bb, 32>>>(feats, mask, tags, trans, (float*)d_out);
}